// round 13
// baseline (speedup 1.0000x reference)
#include <cuda_runtime.h>
#include <cuda_bf16.h>
#include <cstdint>

// Problem constants
#define BATCH 4
#define CH    256
#define NTOK  4096
#define GROUPS 8
#define CPG   (CH / GROUPS)
#define EPSV  1e-5f
#define SCALE 0.0625f         // CH^-0.5

// ---------------------------------------------------------------------------
// Scratch (no cudaMalloc allowed -> __device__ globals)
// ---------------------------------------------------------------------------
__device__ float         g_xn [(size_t)BATCH * CH * NTOK];      // fp32, 16 MB
__device__ __nv_bfloat16 g_qkv[(size_t)BATCH * 3 * CH * NTOK];  // bf16, 25 MB
__device__ float         g_att[(size_t)BATCH * CH * NTOK];      // fp32, 16 MB

// ---------------------------------------------------------------------------
// helpers
// ---------------------------------------------------------------------------
__device__ __forceinline__ uint32_t prmt(uint32_t a, uint32_t b, uint32_t sel) {
    uint32_t d;
    asm("prmt.b32 %0, %1, %2, %3;" : "=r"(d) : "r"(a), "r"(b), "r"(sel));
    return d;
}

__device__ __forceinline__ void cp_async16(void* smem_dst, const void* gsrc) {
    uint32_t s = (uint32_t)__cvta_generic_to_shared(smem_dst);
    asm volatile("cp.async.cg.shared.global [%0], [%1], 16;" :: "r"(s), "l"(gsrc));
}
#define CP_COMMIT() asm volatile("cp.async.commit_group;" ::: "memory")
#define CP_WAIT0()  asm volatile("cp.async.wait_group 0;"  ::: "memory")

#define MMA_BF16(d, a0, a1, a2, a3, b0, b1)                                   \
    asm volatile(                                                             \
        "mma.sync.aligned.m16n8k16.row.col.f32.bf16.bf16.f32 "                \
        "{%0,%1,%2,%3}, {%4,%5,%6,%7}, {%8,%9}, {%0,%1,%2,%3};"               \
        : "+f"((d)[0]), "+f"((d)[1]), "+f"((d)[2]), "+f"((d)[3])              \
        : "r"(a0), "r"(a1), "r"(a2), "r"(a3), "r"(b0), "r"(b1))

// ---------------------------------------------------------------------------
// 1) GroupNorm: one CTA per (batch, group)
// ---------------------------------------------------------------------------
__global__ void __launch_bounds__(256) gn_kernel(
    const float* __restrict__ x, const float* __restrict__ gamma,
    const float* __restrict__ beta, float* __restrict__ xn)
{
    const int b = blockIdx.x >> 3;
    const int g = blockIdx.x & 7;
    const size_t base = ((size_t)b * CH + (size_t)g * CPG) * NTOK;
    const float* xp = x + base;
    const int CNT = CPG * NTOK;

    float s = 0.f, ss = 0.f;
    for (int i = threadIdx.x; i < CNT; i += 256) {
        float v = xp[i];
        s += v; ss += v * v;
    }
#pragma unroll
    for (int off = 16; off; off >>= 1) {
        s  += __shfl_down_sync(0xffffffffu, s,  off);
        ss += __shfl_down_sync(0xffffffffu, ss, off);
    }
    __shared__ float rs[8], rss[8], stats[2];
    const int w = threadIdx.x >> 5, lane = threadIdx.x & 31;
    if (lane == 0) { rs[w] = s; rss[w] = ss; }
    __syncthreads();
    if (threadIdx.x == 0) {
        float S = 0.f, SS = 0.f;
#pragma unroll
        for (int i = 0; i < 8; i++) { S += rs[i]; SS += rss[i]; }
        float mu  = S * (1.f / (float)CNT);
        float var = SS * (1.f / (float)CNT) - mu * mu;
        stats[0] = mu;
        stats[1] = rsqrtf(var + EPSV);
    }
    __syncthreads();
    const float mu = stats[0], rstd = stats[1];
    for (int i = threadIdx.x; i < CNT; i += 256) {
        int c = g * CPG + (i >> 12);
        xn[base + i] = (xp[i] - mu) * rstd * gamma[c] + beta[c];
    }
}

// ---------------------------------------------------------------------------
// 2/4) SIMT tiled GEMM: Y[b,m,n] = sum_k W[m,k]*X[b,k,n] (+bias)(+resid)
//      optional bf16 output
// ---------------------------------------------------------------------------
__global__ void __launch_bounds__(256) gemm64_kernel(
    const float* __restrict__ W, const float* __restrict__ X,
    const float* __restrict__ bias, const float* __restrict__ resid,
    void* __restrict__ Y, int M, int Kd, int out_bf16)
{
    const int Nn = NTOK;
    __shared__ __align__(16) float sA[16][68];
    __shared__ __align__(16) float sB[16][68];

    const int b = blockIdx.z;
    const float* Xb = X + (size_t)b * Kd * Nn;
    const float* Rb = resid ? resid + (size_t)b * (size_t)M * Nn : nullptr;
    const int n0 = blockIdx.x * 64;
    const int m0 = blockIdx.y * 64;
    const int t  = threadIdx.x;
    const int tx = t & 15, ty = t >> 4;

    float acc[4][4] = {};

    for (int k0 = 0; k0 < Kd; k0 += 16) {
#pragma unroll
        for (int i = t; i < 1024; i += 256) {
            int mm = i >> 4, kk = i & 15;
            sA[kk][mm] = W[(size_t)(m0 + mm) * Kd + k0 + kk];
        }
#pragma unroll
        for (int i = t; i < 1024; i += 256) {
            int kk = i >> 6, nn = i & 63;
            sB[kk][nn] = Xb[(size_t)(k0 + kk) * Nn + n0 + nn];
        }
        __syncthreads();
#pragma unroll
        for (int kk = 0; kk < 16; kk++) {
            float4 av = *reinterpret_cast<const float4*>(&sA[kk][ty * 4]);
            float4 bv = *reinterpret_cast<const float4*>(&sB[kk][tx * 4]);
            float ar[4] = {av.x, av.y, av.z, av.w};
            float br[4] = {bv.x, bv.y, bv.z, bv.w};
#pragma unroll
            for (int i = 0; i < 4; i++)
#pragma unroll
                for (int j = 0; j < 4; j++) acc[i][j] += ar[i] * br[j];
        }
        __syncthreads();
    }

    if (out_bf16) {
        __nv_bfloat16* Yb = (__nv_bfloat16*)Y + (size_t)b * (size_t)M * Nn;
#pragma unroll
        for (int i = 0; i < 4; i++) {
            int m = m0 + ty * 4 + i;
            float bi = bias ? bias[m] : 0.f;
#pragma unroll
            for (int j = 0; j < 4; j++) {
                int n = n0 + tx * 4 + j;
                Yb[(size_t)m * Nn + n] = __float2bfloat16(acc[i][j] + bi);
            }
        }
    } else {
        float* Yb = (float*)Y + (size_t)b * (size_t)M * Nn;
#pragma unroll
        for (int i = 0; i < 4; i++) {
            int m = m0 + ty * 4 + i;
            float bi = bias ? bias[m] : 0.f;
#pragma unroll
            for (int j = 0; j < 4; j++) {
                int n = n0 + tx * 4 + j;
                float v = acc[i][j] + bi;
                if (Rb) v += Rb[(size_t)m * Nn + n];
                Yb[(size_t)m * Nn + n] = v;
            }
        }
    }
}

// ---------------------------------------------------------------------------
// 3) Fused flash attention, bf16 m16n8k16 mma, double-buffered K/V.
//    Bq = Bk = 64, C = 256. Grid (N/64, B), 256 threads = 8 warps.
//
//    smem word layouts (uint32 units):
//      sQ,sK : pair layout  word(u, tok) = {x[2u][tok], x[2u+1][tok]},
//              u in [0,128), row stride TPW=72 words   (K double-buffered)
//      sV    : row copy     word(c, tw)  = {v[c][2tw], v[c][2tw+1]},
//              row stride VPW=36 words                  (double-buffered)
//      sS    : fp32 scores [64][SPW=68]
//      sP    : bf16 probs  [64] rows of PPW=36 words (72 bf16)
// ---------------------------------------------------------------------------
#define TPW 72
#define VPW 36
#define PPW 36
#define SPW 68

#define OFF_Q   0
#define OFF_K   (OFF_Q + 128 * TPW)            // 9216
#define OFF_V   (OFF_K + 2 * 128 * TPW)        // 27648
#define OFF_S   (OFF_V + 2 * 256 * VPW)        // 46080
#define OFF_P   (OFF_S + 64 * SPW)             // 50432
#define OFF_MX  (OFF_P + 64 * PPW)             // 52736
#define OFF_L   (OFF_MX + 64)
#define OFF_AL  (OFF_L + 64)
#define SMEM_WORDS (OFF_AL + 64)               // 52928
#define ATTN_SMEM (SMEM_WORDS * 4)             // 211712 B

__global__ void __launch_bounds__(256, 1) attn_kernel(
    const __nv_bfloat16* __restrict__ qkv, float* __restrict__ att)
{
    extern __shared__ uint32_t sm[];
    uint32_t* sQ = sm + OFF_Q;
    uint32_t* sK = sm + OFF_K;
    uint32_t* sV = sm + OFF_V;
    float*    sSf = (float*)(sm + OFF_S);
    uint32_t* sPw = sm + OFF_P;
    __nv_bfloat16* sPh = (__nv_bfloat16*)sPw;
    float* sMx = (float*)(sm + OFF_MX);
    float* sL  = (float*)(sm + OFF_L);
    float* sAl = (float*)(sm + OFF_AL);

    const int tid  = threadIdx.x;
    const int lane = tid & 31;
    const int warp = tid >> 5;
    const int wq = warp >> 1;   // 0..3 : 16-row q block
    const int wk = warp & 1;    // 0..1 : key half (S) / chan half (PV)
    const int r0 = wq * 16;
    const int qr = lane >> 2;   // groupID 0..7
    const int qc = lane & 3;    // threadID-in-group 0..3

    const int b  = blockIdx.y;
    const int n0 = blockIdx.x * 64;
    const uint32_t* qb32 = (const uint32_t*)(qkv + (size_t)b * 3 * CH * NTOK);
    const uint32_t* kb32 = qb32 + (size_t)CH * NTOK / 2;
    const char*     vbytes = (const char*)(kb32 + (size_t)CH * NTOK / 2);

    if (tid < 64) { sMx[tid] = -3.0e38f; sL[tid] = 0.f; }

    // ---- prologue: Q (pair layout), K tile 0, V tile 0 ----
#pragma unroll
    for (int r = 0; r < 16; r++) {
        int p = tid + 256 * r, u = p >> 5, tp = p & 31;
        uint32_t x0 = qb32[(size_t)(2 * u)     * (NTOK / 2) + (n0 >> 1) + tp];
        uint32_t x1 = qb32[(size_t)(2 * u + 1) * (NTOK / 2) + (n0 >> 1) + tp];
        *reinterpret_cast<uint2*>(sQ + u * TPW + 2 * tp) =
            make_uint2(prmt(x0, x1, 0x5410), prmt(x0, x1, 0x7632));
    }
#pragma unroll
    for (int r = 0; r < 16; r++) {
        int p = tid + 256 * r, u = p >> 5, tp = p & 31;
        uint32_t x0 = kb32[(size_t)(2 * u)     * (NTOK / 2) + tp];
        uint32_t x1 = kb32[(size_t)(2 * u + 1) * (NTOK / 2) + tp];
        *reinterpret_cast<uint2*>(sK + u * TPW + 2 * tp) =
            make_uint2(prmt(x0, x1, 0x5410), prmt(x0, x1, 0x7632));
    }
#pragma unroll
    for (int i = 0; i < 8; i++) {
        int q = tid + 256 * i, chan = q >> 3, ch = q & 7;
        cp_async16(sV + chan * VPW + ch * 4,
                   vbytes + ((size_t)chan * NTOK) * 2 + ch * 16);
    }
    CP_COMMIT();
    CP_WAIT0();
    __syncthreads();

    float o[16][4];
#pragma unroll
    for (int nt = 0; nt < 16; nt++)
#pragma unroll
        for (int j = 0; j < 4; j++) o[nt][j] = 0.f;

    for (int kt = 0; kt < NTOK / 64; kt++) {
        const int cur = kt & 1, nxt = cur ^ 1;
        const int m0n = ((kt + 1) & 63) * 64;   // next tile (wraps harmlessly)
        uint32_t* sKc = sK + cur * (128 * TPW);
        uint32_t* sKn = sK + nxt * (128 * TPW);
        uint32_t* sVc = sV + cur * (256 * VPW);
        uint32_t* sVn = sV + nxt * (256 * VPW);

        // async V prefetch for next tile
#pragma unroll
        for (int i = 0; i < 8; i++) {
            int q = tid + 256 * i, chan = q >> 3, ch = q & 7;
            cp_async16(sVn + chan * VPW + ch * 4,
                       vbytes + ((size_t)chan * NTOK + m0n) * 2 + ch * 16);
        }
        CP_COMMIT();

        // K prefetch for next tile into registers (latency hidden by S+softmax)
        uint32_t kr0[16], kr1[16];
#pragma unroll
        for (int r = 0; r < 16; r++) {
            int p = tid + 256 * r, u = p >> 5, tp = p & 31;
            kr0[r] = kb32[(size_t)(2 * u)     * (NTOK / 2) + (m0n >> 1) + tp];
            kr1[r] = kb32[(size_t)(2 * u + 1) * (NTOK / 2) + (m0n >> 1) + tp];
        }

        // ---- S = Q K^T (16 x 32 per warp) ----
        float acc[4][4] = {};
#pragma unroll
        for (int ks = 0; ks < 16; ks++) {
            const int ub = 8 * ks + qc;
            uint32_t a0 = sQ[ub * TPW + r0 + qr];
            uint32_t a1 = sQ[ub * TPW + r0 + qr + 8];
            uint32_t a2 = sQ[(ub + 4) * TPW + r0 + qr];
            uint32_t a3 = sQ[(ub + 4) * TPW + r0 + qr + 8];
#pragma unroll
            for (int nt = 0; nt < 4; nt++) {
                int col = wk * 32 + nt * 8 + qr;
                uint32_t b0 = sKc[ub * TPW + col];
                uint32_t b1 = sKc[(ub + 4) * TPW + col];
                MMA_BF16(acc[nt], a0, a1, a2, a3, b0, b1);
            }
        }
#pragma unroll
        for (int nt = 0; nt < 4; nt++) {
            int colb = wk * 32 + nt * 8 + 2 * qc;
            int rr = r0 + qr;
            sSf[rr * SPW + colb]           = acc[nt][0] * SCALE;
            sSf[rr * SPW + colb + 1]       = acc[nt][1] * SCALE;
            sSf[(rr + 8) * SPW + colb]     = acc[nt][2] * SCALE;
            sSf[(rr + 8) * SPW + colb + 1] = acc[nt][3] * SCALE;
        }
        asm volatile("bar.sync %0, 64;" :: "r"(1 + wq) : "memory");

        // ---- online softmax (pair-local): 4 lanes per row ----
        {
            int row = tid >> 2, sub = tid & 3;
            float mold = sMx[row];
            float mx = mold;
#pragma unroll
            for (int j = sub; j < 64; j += 4) mx = fmaxf(mx, sSf[row * SPW + j]);
            mx = fmaxf(mx, __shfl_xor_sync(0xffffffffu, mx, 1));
            mx = fmaxf(mx, __shfl_xor_sync(0xffffffffu, mx, 2));
            float lsum = 0.f;
#pragma unroll
            for (int j = sub; j < 64; j += 4) {
                float pv = __expf(sSf[row * SPW + j] - mx);
                sPh[row * (PPW * 2) + j] = __float2bfloat16(pv);
                lsum += pv;
            }
            lsum += __shfl_xor_sync(0xffffffffu, lsum, 1);
            lsum += __shfl_xor_sync(0xffffffffu, lsum, 2);
            if (sub == 0) {
                float alpha = __expf(mold - mx);
                sAl[row] = alpha;
                sMx[row] = mx;
                sL[row]  = sL[row] * alpha + lsum;
            }
        }
        asm volatile("bar.sync %0, 64;" :: "r"(1 + wq) : "memory");

        // ---- store K(next) : PRMT pack + STS.64, 2-wavefront pattern ----
#pragma unroll
        for (int r = 0; r < 16; r++) {
            int p = tid + 256 * r, u = p >> 5, tp = p & 31;
            *reinterpret_cast<uint2*>(sKn + u * TPW + 2 * tp) =
                make_uint2(prmt(kr0[r], kr1[r], 0x5410),
                           prmt(kr0[r], kr1[r], 0x7632));
        }

        // ---- rescale O, then O += P * V  (16 x 128 per warp) ----
        float aLo = sAl[r0 + qr];
        float aHi = sAl[r0 + qr + 8];
#pragma unroll
        for (int nt = 0; nt < 16; nt++) {
            o[nt][0] *= aLo; o[nt][1] *= aLo;
            o[nt][2] *= aHi; o[nt][3] *= aHi;
        }
#pragma unroll
        for (int ks = 0; ks < 4; ks++) {
            const int ub = 8 * ks + qc;
            uint32_t a0 = sPw[(r0 + qr) * PPW + ub];
            uint32_t a1 = sPw[(r0 + qr + 8) * PPW + ub];
            uint32_t a2 = sPw[(r0 + qr) * PPW + ub + 4];
            uint32_t a3 = sPw[(r0 + qr + 8) * PPW + ub + 4];
#pragma unroll
            for (int nt = 0; nt < 16; nt++) {
                int chan = wk * 128 + nt * 8 + qr;
                uint32_t b0 = sVc[chan * VPW + ub];
                uint32_t b1 = sVc[chan * VPW + ub + 4];
                MMA_BF16(o[nt], a0, a1, a2, a3, b0, b1);
            }
        }
        CP_WAIT0();
        __syncthreads();
    }

    // ---- epilogue: divide by l, write att[b, c, n] (fp32) ----
    const float lLo = 1.f / sL[r0 + qr];
    const float lHi = 1.f / sL[r0 + qr + 8];
    float* ab = att + (size_t)b * CH * NTOK;
    const int nLo = n0 + r0 + qr;
    const int nHi = nLo + 8;
#pragma unroll
    for (int nt = 0; nt < 16; nt++) {
        int c = wk * 128 + nt * 8 + 2 * qc;
        ab[(size_t)c * NTOK + nLo]       = o[nt][0] * lLo;
        ab[(size_t)(c + 1) * NTOK + nLo] = o[nt][1] * lLo;
        ab[(size_t)c * NTOK + nHi]       = o[nt][2] * lHi;
        ab[(size_t)(c + 1) * NTOK + nHi] = o[nt][3] * lHi;
    }
}

// ---------------------------------------------------------------------------
// launch
// ---------------------------------------------------------------------------
extern "C" void kernel_launch(void* const* d_in, const int* in_sizes, int n_in,
                              void* d_out, int out_size)
{
    const float* x      = (const float*)d_in[0];
    const float* gamma  = (const float*)d_in[1];
    const float* beta   = (const float*)d_in[2];
    const float* w_qkv  = (const float*)d_in[3];
    const float* w_proj = (const float*)d_in[4];
    const float* b_proj = (const float*)d_in[5];
    float* out = (float*)d_out;

    float *xn, *att;
    __nv_bfloat16* qkv;
    cudaGetSymbolAddress((void**)&xn,  g_xn);
    cudaGetSymbolAddress((void**)&qkv, g_qkv);
    cudaGetSymbolAddress((void**)&att, g_att);

    // 1) GroupNorm
    gn_kernel<<<BATCH * GROUPS, 256>>>(x, gamma, beta, xn);

    // 2) QKV = W_qkv @ xn  -> bf16
    gemm64_kernel<<<dim3(NTOK / 64, (3 * CH) / 64, BATCH), 256>>>(
        w_qkv, xn, nullptr, nullptr, qkv, 3 * CH, CH, 1);

    // 3) fused flash attention (bf16 mma, pipelined)
    cudaFuncSetAttribute(attn_kernel,
                         cudaFuncAttributeMaxDynamicSharedMemorySize, ATTN_SMEM);
    attn_kernel<<<dim3(NTOK / 64, BATCH), 256, ATTN_SMEM>>>(qkv, att);

    // 4) out = x + W_proj @ att + b_proj
    gemm64_kernel<<<dim3(NTOK / 64, CH / 64, BATCH), 256>>>(
        w_proj, att, b_proj, x, out, CH, CH, 0);
}

// round 14
// speedup vs baseline: 1.3396x; 1.3396x over previous
#include <cuda_runtime.h>
#include <cuda_bf16.h>
#include <cstdint>

// Problem constants
#define BATCH 4
#define CH    256
#define NTOK  4096
#define GROUPS 8
#define CPG   (CH / GROUPS)
#define EPSV  1e-5f
#define SCALE 0.0625f         // CH^-0.5

// ---------------------------------------------------------------------------
// Scratch (no cudaMalloc allowed -> __device__ globals)
// ---------------------------------------------------------------------------
__device__ __nv_bfloat16 g_xn [(size_t)BATCH * CH * NTOK];      // 8 MB
__device__ __nv_bfloat16 g_qkv[(size_t)BATCH * 3 * CH * NTOK];  // 25 MB
__device__ __nv_bfloat16 g_att[(size_t)BATCH * CH * NTOK];      // 8 MB
__device__ __nv_bfloat16 g_wqkv_h[3 * CH * CH];                 // 384 KB
__device__ __nv_bfloat16 g_wproj_h[CH * CH];                    // 128 KB

// ---------------------------------------------------------------------------
// helpers
// ---------------------------------------------------------------------------
__device__ __forceinline__ uint32_t prmt(uint32_t a, uint32_t b, uint32_t sel) {
    uint32_t d;
    asm("prmt.b32 %0, %1, %2, %3;" : "=r"(d) : "r"(a), "r"(b), "r"(sel));
    return d;
}

__device__ __forceinline__ void cp_async16(void* smem_dst, const void* gsrc) {
    uint32_t s = (uint32_t)__cvta_generic_to_shared(smem_dst);
    asm volatile("cp.async.cg.shared.global [%0], [%1], 16;" :: "r"(s), "l"(gsrc));
}
#define CP_COMMIT() asm volatile("cp.async.commit_group;" ::: "memory")
#define CP_WAIT0()  asm volatile("cp.async.wait_group 0;"  ::: "memory")

#define MMA_BF16(d, a0, a1, a2, a3, b0, b1)                                   \
    asm volatile(                                                             \
        "mma.sync.aligned.m16n8k16.row.col.f32.bf16.bf16.f32 "                \
        "{%0,%1,%2,%3}, {%4,%5,%6,%7}, {%8,%9}, {%0,%1,%2,%3};"               \
        : "+f"((d)[0]), "+f"((d)[1]), "+f"((d)[2]), "+f"((d)[3])              \
        : "r"(a0), "r"(a1), "r"(a2), "r"(a3), "r"(b0), "r"(b1))

// ---------------------------------------------------------------------------
// 0) weight fp32 -> bf16 conversion (runs every launch; deterministic)
// ---------------------------------------------------------------------------
__global__ void __launch_bounds__(256) cvt_w_kernel(
    const float* __restrict__ wq, const float* __restrict__ wp,
    __nv_bfloat16* __restrict__ wqh, __nv_bfloat16* __restrict__ wph)
{
    const int stride = gridDim.x * 256;
    for (int p = blockIdx.x * 256 + threadIdx.x; p < 3 * CH * CH; p += stride)
        wqh[p] = __float2bfloat16(wq[p]);
    for (int p = blockIdx.x * 256 + threadIdx.x; p < CH * CH; p += stride)
        wph[p] = __float2bfloat16(wp[p]);
}

// ---------------------------------------------------------------------------
// 1) GroupNorm: one CTA per (batch, group). bf16 output.
// ---------------------------------------------------------------------------
__global__ void __launch_bounds__(256) gn_kernel(
    const float* __restrict__ x, const float* __restrict__ gamma,
    const float* __restrict__ beta, __nv_bfloat16* __restrict__ xn)
{
    const int b = blockIdx.x >> 3;
    const int g = blockIdx.x & 7;
    const size_t base = ((size_t)b * CH + (size_t)g * CPG) * NTOK;
    const float* xp = x + base;
    const int CNT = CPG * NTOK;

    float s = 0.f, ss = 0.f;
    for (int i = threadIdx.x; i < CNT; i += 256) {
        float v = xp[i];
        s += v; ss += v * v;
    }
#pragma unroll
    for (int off = 16; off; off >>= 1) {
        s  += __shfl_down_sync(0xffffffffu, s,  off);
        ss += __shfl_down_sync(0xffffffffu, ss, off);
    }
    __shared__ float rs[8], rss[8], stats[2];
    const int w = threadIdx.x >> 5, lane = threadIdx.x & 31;
    if (lane == 0) { rs[w] = s; rss[w] = ss; }
    __syncthreads();
    if (threadIdx.x == 0) {
        float S = 0.f, SS = 0.f;
#pragma unroll
        for (int i = 0; i < 8; i++) { S += rs[i]; SS += rss[i]; }
        float mu  = S * (1.f / (float)CNT);
        float var = SS * (1.f / (float)CNT) - mu * mu;
        stats[0] = mu;
        stats[1] = rsqrtf(var + EPSV);
    }
    __syncthreads();
    const float mu = stats[0], rstd = stats[1];
    for (int i = threadIdx.x; i < CNT; i += 256) {
        int c = g * CPG + (i >> 12);
        xn[base + i] = __float2bfloat16((xp[i] - mu) * rstd * gamma[c] + beta[c]);
    }
}

// ---------------------------------------------------------------------------
// 2/4) bf16 mma GEMM: Y[b,m,n] = sum_k W[m,k]*X[b,k,n] (+bias)(+resid)
//      CTA tile 64m x 64n, full K=256 staged in smem once.
//      sW: [m][u] stride 132 (u = k/2 bf16-pair words), loaded via cp.async
//      sX: [u][n] stride 72, PRMT-packed (pairs along k), attention-proven
//      Warp (wq = warp>>1, wk = warp&1): 16m x 32n, acc[4][4].
// ---------------------------------------------------------------------------
#define GW_STRIDE 132
#define GX_STRIDE 72
#define GEMM_SMEM ((64 * GW_STRIDE + 128 * GX_STRIDE) * 4)   // 70656 B

__global__ void __launch_bounds__(256, 2) mma_gemm_kernel(
    const __nv_bfloat16* __restrict__ Wh,   // [M, K=256] bf16 row-major
    const __nv_bfloat16* __restrict__ X,    // [B][K=256][N=4096] bf16
    const float* __restrict__ bias,         // [M] or null
    const float* __restrict__ resid,        // [B][M][N] fp32 or null
    void* __restrict__ Y, int M, int out_bf16)
{
    extern __shared__ uint32_t smg[];
    uint32_t* sW = smg;                     // 64 * 132
    uint32_t* sX = smg + 64 * GW_STRIDE;    // 128 * 72

    const int b  = blockIdx.z;
    const int n0 = blockIdx.x * 64;
    const int m0 = blockIdx.y * 64;
    const int tid = threadIdx.x, lane = tid & 31, warp = tid >> 5;
    const int wq = warp >> 1, wk = warp & 1;
    const int r0 = wq * 16, qr = lane >> 2, qc = lane & 3;

    const uint32_t* Ww = (const uint32_t*)Wh;                       // 128 words/row
    const uint32_t* Xw = (const uint32_t*)(X + (size_t)b * CH * NTOK);

    // W tile: 64 rows x 128 words, coalesced 16B cp.async
#pragma unroll
    for (int i = 0; i < 8; i++) {
        int p = tid + 256 * i;          // 0..2047
        int m = p >> 5, j = p & 31;
        cp_async16(sW + m * GW_STRIDE + 4 * j,
                   Ww + (size_t)(m0 + m) * 128 + 4 * j);
    }
    CP_COMMIT();

    // X tile: pairs along k, [u][n] layout (PRMT pack, STS.64)
#pragma unroll
    for (int r = 0; r < 16; r++) {
        int p = tid + 256 * r;          // 0..4095
        int u = p >> 5, tp = p & 31;
        uint32_t x0 = Xw[(size_t)(2 * u)     * (NTOK / 2) + (n0 >> 1) + tp];
        uint32_t x1 = Xw[(size_t)(2 * u + 1) * (NTOK / 2) + (n0 >> 1) + tp];
        *reinterpret_cast<uint2*>(sX + u * GX_STRIDE + 2 * tp) =
            make_uint2(prmt(x0, x1, 0x5410), prmt(x0, x1, 0x7632));
    }
    CP_WAIT0();
    __syncthreads();

    float acc[4][4] = {};
#pragma unroll
    for (int ks = 0; ks < 16; ks++) {
        const int ub = 8 * ks + qc;
        uint32_t a0 = sW[(r0 + qr) * GW_STRIDE + ub];
        uint32_t a1 = sW[(r0 + qr + 8) * GW_STRIDE + ub];
        uint32_t a2 = sW[(r0 + qr) * GW_STRIDE + ub + 4];
        uint32_t a3 = sW[(r0 + qr + 8) * GW_STRIDE + ub + 4];
#pragma unroll
        for (int nt = 0; nt < 4; nt++) {
            int col = wk * 32 + nt * 8 + qr;
            uint32_t b0 = sX[ub * GX_STRIDE + col];
            uint32_t b1 = sX[(ub + 4) * GX_STRIDE + col];
            MMA_BF16(acc[nt], a0, a1, a2, a3, b0, b1);
        }
    }

    // epilogue
    if (out_bf16) {
        uint32_t* Yb = (uint32_t*)Y + (size_t)b * (size_t)M * (NTOK / 2);
#pragma unroll
        for (int nt = 0; nt < 4; nt++) {
            int col = wk * 32 + nt * 8 + 2 * qc;        // even
            int m = m0 + r0 + qr;
            __nv_bfloat162 lo = {__float2bfloat16(acc[nt][0]),
                                 __float2bfloat16(acc[nt][1])};
            __nv_bfloat162 hi = {__float2bfloat16(acc[nt][2]),
                                 __float2bfloat16(acc[nt][3])};
            Yb[(size_t)m * (NTOK / 2) + ((n0 + col) >> 1)]       = *(uint32_t*)&lo;
            Yb[(size_t)(m + 8) * (NTOK / 2) + ((n0 + col) >> 1)] = *(uint32_t*)&hi;
        }
    } else {
        float* Yb = (float*)Y + (size_t)b * (size_t)M * NTOK;
        const float* Rb = resid + (size_t)b * (size_t)M * NTOK;
#pragma unroll
        for (int nt = 0; nt < 4; nt++) {
            int col = n0 + wk * 32 + nt * 8 + 2 * qc;
            int m = m0 + r0 + qr;
            float bi0 = bias ? bias[m] : 0.f;
            float bi1 = bias ? bias[m + 8] : 0.f;
            float2 r0v = *reinterpret_cast<const float2*>(&Rb[(size_t)m * NTOK + col]);
            float2 r1v = *reinterpret_cast<const float2*>(&Rb[(size_t)(m + 8) * NTOK + col]);
            float2 v0 = {acc[nt][0] + bi0 + r0v.x, acc[nt][1] + bi0 + r0v.y};
            float2 v1 = {acc[nt][2] + bi1 + r1v.x, acc[nt][3] + bi1 + r1v.y};
            *reinterpret_cast<float2*>(&Yb[(size_t)m * NTOK + col]) = v0;
            *reinterpret_cast<float2*>(&Yb[(size_t)(m + 8) * NTOK + col]) = v1;
        }
    }
}

// ---------------------------------------------------------------------------
// 3) Fused flash attention, bf16 m16n8k16 mma, double-buffered K/V.
//    (unchanged from R13 except bf16 epilogue)
// ---------------------------------------------------------------------------
#define TPW 72
#define VPW 36
#define PPW 36
#define SPW 68

#define OFF_Q   0
#define OFF_K   (OFF_Q + 128 * TPW)
#define OFF_V   (OFF_K + 2 * 128 * TPW)
#define OFF_S   (OFF_V + 2 * 256 * VPW)
#define OFF_P   (OFF_S + 64 * SPW)
#define OFF_MX  (OFF_P + 64 * PPW)
#define OFF_L   (OFF_MX + 64)
#define OFF_AL  (OFF_L + 64)
#define SMEM_WORDS (OFF_AL + 64)
#define ATTN_SMEM (SMEM_WORDS * 4)             // 211712 B

__global__ void __launch_bounds__(256, 1) attn_kernel(
    const __nv_bfloat16* __restrict__ qkv, __nv_bfloat16* __restrict__ att)
{
    extern __shared__ uint32_t sm[];
    uint32_t* sQ = sm + OFF_Q;
    uint32_t* sK = sm + OFF_K;
    uint32_t* sV = sm + OFF_V;
    float*    sSf = (float*)(sm + OFF_S);
    uint32_t* sPw = sm + OFF_P;
    __nv_bfloat16* sPh = (__nv_bfloat16*)sPw;
    float* sMx = (float*)(sm + OFF_MX);
    float* sL  = (float*)(sm + OFF_L);
    float* sAl = (float*)(sm + OFF_AL);

    const int tid  = threadIdx.x;
    const int lane = tid & 31;
    const int warp = tid >> 5;
    const int wq = warp >> 1;
    const int wk = warp & 1;
    const int r0 = wq * 16;
    const int qr = lane >> 2;
    const int qc = lane & 3;

    const int b  = blockIdx.y;
    const int n0 = blockIdx.x * 64;
    const uint32_t* qb32 = (const uint32_t*)(qkv + (size_t)b * 3 * CH * NTOK);
    const uint32_t* kb32 = qb32 + (size_t)CH * NTOK / 2;
    const char*     vbytes = (const char*)(kb32 + (size_t)CH * NTOK / 2);

    if (tid < 64) { sMx[tid] = -3.0e38f; sL[tid] = 0.f; }

    // prologue: Q (pair layout), K tile 0, V tile 0
#pragma unroll
    for (int r = 0; r < 16; r++) {
        int p = tid + 256 * r, u = p >> 5, tp = p & 31;
        uint32_t x0 = qb32[(size_t)(2 * u)     * (NTOK / 2) + (n0 >> 1) + tp];
        uint32_t x1 = qb32[(size_t)(2 * u + 1) * (NTOK / 2) + (n0 >> 1) + tp];
        *reinterpret_cast<uint2*>(sQ + u * TPW + 2 * tp) =
            make_uint2(prmt(x0, x1, 0x5410), prmt(x0, x1, 0x7632));
    }
#pragma unroll
    for (int r = 0; r < 16; r++) {
        int p = tid + 256 * r, u = p >> 5, tp = p & 31;
        uint32_t x0 = kb32[(size_t)(2 * u)     * (NTOK / 2) + tp];
        uint32_t x1 = kb32[(size_t)(2 * u + 1) * (NTOK / 2) + tp];
        *reinterpret_cast<uint2*>(sK + u * TPW + 2 * tp) =
            make_uint2(prmt(x0, x1, 0x5410), prmt(x0, x1, 0x7632));
    }
#pragma unroll
    for (int i = 0; i < 8; i++) {
        int q = tid + 256 * i, chan = q >> 3, ch = q & 7;
        cp_async16(sV + chan * VPW + ch * 4,
                   vbytes + ((size_t)chan * NTOK) * 2 + ch * 16);
    }
    CP_COMMIT();
    CP_WAIT0();
    __syncthreads();

    float o[16][4];
#pragma unroll
    for (int nt = 0; nt < 16; nt++)
#pragma unroll
        for (int j = 0; j < 4; j++) o[nt][j] = 0.f;

    for (int kt = 0; kt < NTOK / 64; kt++) {
        const int cur = kt & 1, nxt = cur ^ 1;
        const int m0n = ((kt + 1) & 63) * 64;
        uint32_t* sKc = sK + cur * (128 * TPW);
        uint32_t* sKn = sK + nxt * (128 * TPW);
        uint32_t* sVc = sV + cur * (256 * VPW);
        uint32_t* sVn = sV + nxt * (256 * VPW);

#pragma unroll
        for (int i = 0; i < 8; i++) {
            int q = tid + 256 * i, chan = q >> 3, ch = q & 7;
            cp_async16(sVn + chan * VPW + ch * 4,
                       vbytes + ((size_t)chan * NTOK + m0n) * 2 + ch * 16);
        }
        CP_COMMIT();

        uint32_t kr0[16], kr1[16];
#pragma unroll
        for (int r = 0; r < 16; r++) {
            int p = tid + 256 * r, u = p >> 5, tp = p & 31;
            kr0[r] = kb32[(size_t)(2 * u)     * (NTOK / 2) + (m0n >> 1) + tp];
            kr1[r] = kb32[(size_t)(2 * u + 1) * (NTOK / 2) + (m0n >> 1) + tp];
        }

        // S = Q K^T
        float acc[4][4] = {};
#pragma unroll
        for (int ks = 0; ks < 16; ks++) {
            const int ub = 8 * ks + qc;
            uint32_t a0 = sQ[ub * TPW + r0 + qr];
            uint32_t a1 = sQ[ub * TPW + r0 + qr + 8];
            uint32_t a2 = sQ[(ub + 4) * TPW + r0 + qr];
            uint32_t a3 = sQ[(ub + 4) * TPW + r0 + qr + 8];
#pragma unroll
            for (int nt = 0; nt < 4; nt++) {
                int col = wk * 32 + nt * 8 + qr;
                uint32_t b0 = sKc[ub * TPW + col];
                uint32_t b1 = sKc[(ub + 4) * TPW + col];
                MMA_BF16(acc[nt], a0, a1, a2, a3, b0, b1);
            }
        }
#pragma unroll
        for (int nt = 0; nt < 4; nt++) {
            int colb = wk * 32 + nt * 8 + 2 * qc;
            int rr = r0 + qr;
            sSf[rr * SPW + colb]           = acc[nt][0] * SCALE;
            sSf[rr * SPW + colb + 1]       = acc[nt][1] * SCALE;
            sSf[(rr + 8) * SPW + colb]     = acc[nt][2] * SCALE;
            sSf[(rr + 8) * SPW + colb + 1] = acc[nt][3] * SCALE;
        }
        asm volatile("bar.sync %0, 64;" :: "r"(1 + wq) : "memory");

        // online softmax
        {
            int row = tid >> 2, sub = tid & 3;
            float mold = sMx[row];
            float mx = mold;
#pragma unroll
            for (int j = sub; j < 64; j += 4) mx = fmaxf(mx, sSf[row * SPW + j]);
            mx = fmaxf(mx, __shfl_xor_sync(0xffffffffu, mx, 1));
            mx = fmaxf(mx, __shfl_xor_sync(0xffffffffu, mx, 2));
            float lsum = 0.f;
#pragma unroll
            for (int j = sub; j < 64; j += 4) {
                float pv = __expf(sSf[row * SPW + j] - mx);
                sPh[row * (PPW * 2) + j] = __float2bfloat16(pv);
                lsum += pv;
            }
            lsum += __shfl_xor_sync(0xffffffffu, lsum, 1);
            lsum += __shfl_xor_sync(0xffffffffu, lsum, 2);
            if (sub == 0) {
                float alpha = __expf(mold - mx);
                sAl[row] = alpha;
                sMx[row] = mx;
                sL[row]  = sL[row] * alpha + lsum;
            }
        }
        asm volatile("bar.sync %0, 64;" :: "r"(1 + wq) : "memory");

        // store K(next)
#pragma unroll
        for (int r = 0; r < 16; r++) {
            int p = tid + 256 * r, u = p >> 5, tp = p & 31;
            *reinterpret_cast<uint2*>(sKn + u * TPW + 2 * tp) =
                make_uint2(prmt(kr0[r], kr1[r], 0x5410),
                           prmt(kr0[r], kr1[r], 0x7632));
        }

        // rescale O, then O += P * V
        float aLo = sAl[r0 + qr];
        float aHi = sAl[r0 + qr + 8];
#pragma unroll
        for (int nt = 0; nt < 16; nt++) {
            o[nt][0] *= aLo; o[nt][1] *= aLo;
            o[nt][2] *= aHi; o[nt][3] *= aHi;
        }
#pragma unroll
        for (int ks = 0; ks < 4; ks++) {
            const int ub = 8 * ks + qc;
            uint32_t a0 = sPw[(r0 + qr) * PPW + ub];
            uint32_t a1 = sPw[(r0 + qr + 8) * PPW + ub];
            uint32_t a2 = sPw[(r0 + qr) * PPW + ub + 4];
            uint32_t a3 = sPw[(r0 + qr + 8) * PPW + ub + 4];
#pragma unroll
            for (int nt = 0; nt < 16; nt++) {
                int chan = wk * 128 + nt * 8 + qr;
                uint32_t b0 = sVc[chan * VPW + ub];
                uint32_t b1 = sVc[chan * VPW + ub + 4];
                MMA_BF16(o[nt], a0, a1, a2, a3, b0, b1);
            }
        }
        CP_WAIT0();
        __syncthreads();
    }

    // epilogue: divide by l, write bf16 att[b, c, n]
    const float lLo = 1.f / sL[r0 + qr];
    const float lHi = 1.f / sL[r0 + qr + 8];
    __nv_bfloat16* ab = att + (size_t)b * CH * NTOK;
    const int nLo = n0 + r0 + qr;
    const int nHi = nLo + 8;
#pragma unroll
    for (int nt = 0; nt < 16; nt++) {
        int c = wk * 128 + nt * 8 + 2 * qc;
        ab[(size_t)c * NTOK + nLo]       = __float2bfloat16(o[nt][0] * lLo);
        ab[(size_t)(c + 1) * NTOK + nLo] = __float2bfloat16(o[nt][1] * lLo);
        ab[(size_t)c * NTOK + nHi]       = __float2bfloat16(o[nt][2] * lHi);
        ab[(size_t)(c + 1) * NTOK + nHi] = __float2bfloat16(o[nt][3] * lHi);
    }
}

// ---------------------------------------------------------------------------
// launch
// ---------------------------------------------------------------------------
extern "C" void kernel_launch(void* const* d_in, const int* in_sizes, int n_in,
                              void* d_out, int out_size)
{
    const float* x      = (const float*)d_in[0];
    const float* gamma  = (const float*)d_in[1];
    const float* beta   = (const float*)d_in[2];
    const float* w_qkv  = (const float*)d_in[3];
    const float* w_proj = (const float*)d_in[4];
    const float* b_proj = (const float*)d_in[5];
    float* out = (float*)d_out;

    __nv_bfloat16 *xn, *qkv, *att, *wqh, *wph;
    cudaGetSymbolAddress((void**)&xn,  g_xn);
    cudaGetSymbolAddress((void**)&qkv, g_qkv);
    cudaGetSymbolAddress((void**)&att, g_att);
    cudaGetSymbolAddress((void**)&wqh, g_wqkv_h);
    cudaGetSymbolAddress((void**)&wph, g_wproj_h);

    // 0) convert weights to bf16
    cvt_w_kernel<<<192, 256>>>(w_qkv, w_proj, wqh, wph);

    // 1) GroupNorm -> bf16
    gn_kernel<<<BATCH * GROUPS, 256>>>(x, gamma, beta, xn);

    // 2) QKV = W_qkv @ xn  -> bf16  (mma)
    cudaFuncSetAttribute(mma_gemm_kernel,
                         cudaFuncAttributeMaxDynamicSharedMemorySize, GEMM_SMEM);
    mma_gemm_kernel<<<dim3(NTOK / 64, (3 * CH) / 64, BATCH), 256, GEMM_SMEM>>>(
        wqh, xn, nullptr, nullptr, qkv, 3 * CH, 1);

    // 3) fused flash attention (bf16 mma, pipelined) -> bf16 att
    cudaFuncSetAttribute(attn_kernel,
                         cudaFuncAttributeMaxDynamicSharedMemorySize, ATTN_SMEM);
    attn_kernel<<<dim3(NTOK / 64, BATCH), 256, ATTN_SMEM>>>(qkv, att);

    // 4) out = x + W_proj @ att + b_proj  (mma, fp32 out)
    mma_gemm_kernel<<<dim3(NTOK / 64, CH / 64, BATCH), 256, GEMM_SMEM>>>(
        wph, att, b_proj, x, out, CH, 0);
}

// round 15
// speedup vs baseline: 1.3426x; 1.0023x over previous
#include <cuda_runtime.h>
#include <cuda_bf16.h>
#include <cstdint>

// Problem constants
#define BATCH 4
#define CH    256
#define NTOK  4096
#define GROUPS 8
#define CPG   (CH / GROUPS)
#define EPSV  1e-5f
#define SCALE 0.0625f         // CH^-0.5

// ---------------------------------------------------------------------------
// Scratch (no cudaMalloc allowed -> __device__ globals)
// ---------------------------------------------------------------------------
__device__ __nv_bfloat16 g_xn [(size_t)BATCH * CH * NTOK];      // 8 MB
__device__ __nv_bfloat16 g_qkv[(size_t)BATCH * 3 * CH * NTOK];  // 25 MB
__device__ __nv_bfloat16 g_att[(size_t)BATCH * CH * NTOK];      // 8 MB
__device__ __nv_bfloat16 g_wqkv_h[3 * CH * CH];                 // 384 KB
__device__ __nv_bfloat16 g_wproj_h[CH * CH];                    // 128 KB

// ---------------------------------------------------------------------------
// helpers
// ---------------------------------------------------------------------------
__device__ __forceinline__ uint32_t prmt(uint32_t a, uint32_t b, uint32_t sel) {
    uint32_t d;
    asm("prmt.b32 %0, %1, %2, %3;" : "=r"(d) : "r"(a), "r"(b), "r"(sel));
    return d;
}

__device__ __forceinline__ void cp_async16(void* smem_dst, const void* gsrc) {
    uint32_t s = (uint32_t)__cvta_generic_to_shared(smem_dst);
    asm volatile("cp.async.cg.shared.global [%0], [%1], 16;" :: "r"(s), "l"(gsrc));
}
#define CP_COMMIT() asm volatile("cp.async.commit_group;" ::: "memory")
#define CP_WAIT0()  asm volatile("cp.async.wait_group 0;"  ::: "memory")

#define MMA_BF16(d, a0, a1, a2, a3, b0, b1)                                   \
    asm volatile(                                                             \
        "mma.sync.aligned.m16n8k16.row.col.f32.bf16.bf16.f32 "                \
        "{%0,%1,%2,%3}, {%4,%5,%6,%7}, {%8,%9}, {%0,%1,%2,%3};"               \
        : "+f"((d)[0]), "+f"((d)[1]), "+f"((d)[2]), "+f"((d)[3])              \
        : "r"(a0), "r"(a1), "r"(a2), "r"(a3), "r"(b0), "r"(b1))

// ---------------------------------------------------------------------------
// 0) weight fp32 -> bf16 conversion (runs every launch; deterministic)
// ---------------------------------------------------------------------------
__global__ void __launch_bounds__(256) cvt_w_kernel(
    const float* __restrict__ wq, const float* __restrict__ wp,
    __nv_bfloat16* __restrict__ wqh, __nv_bfloat16* __restrict__ wph)
{
    const int stride = gridDim.x * 256;
    for (int p = blockIdx.x * 256 + threadIdx.x; p < 3 * CH * CH; p += stride)
        wqh[p] = __float2bfloat16(wq[p]);
    for (int p = blockIdx.x * 256 + threadIdx.x; p < CH * CH; p += stride)
        wph[p] = __float2bfloat16(wp[p]);
}

// ---------------------------------------------------------------------------
// 1) GroupNorm: one CTA per (batch, group). bf16 output.
// ---------------------------------------------------------------------------
__global__ void __launch_bounds__(256) gn_kernel(
    const float* __restrict__ x, const float* __restrict__ gamma,
    const float* __restrict__ beta, __nv_bfloat16* __restrict__ xn)
{
    const int b = blockIdx.x >> 3;
    const int g = blockIdx.x & 7;
    const size_t base = ((size_t)b * CH + (size_t)g * CPG) * NTOK;
    const float* xp = x + base;
    const int CNT = CPG * NTOK;

    float s = 0.f, ss = 0.f;
    for (int i = threadIdx.x; i < CNT; i += 256) {
        float v = xp[i];
        s += v; ss += v * v;
    }
#pragma unroll
    for (int off = 16; off; off >>= 1) {
        s  += __shfl_down_sync(0xffffffffu, s,  off);
        ss += __shfl_down_sync(0xffffffffu, ss, off);
    }
    __shared__ float rs[8], rss[8], stats[2];
    const int w = threadIdx.x >> 5, lane = threadIdx.x & 31;
    if (lane == 0) { rs[w] = s; rss[w] = ss; }
    __syncthreads();
    if (threadIdx.x == 0) {
        float S = 0.f, SS = 0.f;
#pragma unroll
        for (int i = 0; i < 8; i++) { S += rs[i]; SS += rss[i]; }
        float mu  = S * (1.f / (float)CNT);
        float var = SS * (1.f / (float)CNT) - mu * mu;
        stats[0] = mu;
        stats[1] = rsqrtf(var + EPSV);
    }
    __syncthreads();
    const float mu = stats[0], rstd = stats[1];
    for (int i = threadIdx.x; i < CNT; i += 256) {
        int c = g * CPG + (i >> 12);
        xn[base + i] = __float2bfloat16((xp[i] - mu) * rstd * gamma[c] + beta[c]);
    }
}

// ---------------------------------------------------------------------------
// 2/4) bf16 mma GEMM: Y[b,m,n] = sum_k W[m,k]*X[b,k,n] (+bias)(+resid)
//      CTA tile 64m x 64n, full K=256 staged in smem once.
//      sW: [m][u] stride 132 (u = k/2 bf16-pair words), loaded via cp.async
//      sX: [u][n] stride 72, PRMT-packed (pairs along k), attention-proven
//      Warp (wq = warp>>1, wk = warp&1): 16m x 32n, acc[4][4].
// ---------------------------------------------------------------------------
#define GW_STRIDE 132
#define GX_STRIDE 72
#define GEMM_SMEM ((64 * GW_STRIDE + 128 * GX_STRIDE) * 4)   // 70656 B

__global__ void __launch_bounds__(256, 2) mma_gemm_kernel(
    const __nv_bfloat16* __restrict__ Wh,   // [M, K=256] bf16 row-major
    const __nv_bfloat16* __restrict__ X,    // [B][K=256][N=4096] bf16
    const float* __restrict__ bias,         // [M] or null
    const float* __restrict__ resid,        // [B][M][N] fp32 or null
    void* __restrict__ Y, int M, int out_bf16)
{
    extern __shared__ uint32_t smg[];
    uint32_t* sW = smg;                     // 64 * 132
    uint32_t* sX = smg + 64 * GW_STRIDE;    // 128 * 72

    const int b  = blockIdx.z;
    const int n0 = blockIdx.x * 64;
    const int m0 = blockIdx.y * 64;
    const int tid = threadIdx.x, lane = tid & 31, warp = tid >> 5;
    const int wq = warp >> 1, wk = warp & 1;
    const int r0 = wq * 16, qr = lane >> 2, qc = lane & 3;

    const uint32_t* Ww = (const uint32_t*)Wh;                       // 128 words/row
    const uint32_t* Xw = (const uint32_t*)(X + (size_t)b * CH * NTOK);

    // W tile: 64 rows x 128 words, coalesced 16B cp.async
#pragma unroll
    for (int i = 0; i < 8; i++) {
        int p = tid + 256 * i;          // 0..2047
        int m = p >> 5, j = p & 31;
        cp_async16(sW + m * GW_STRIDE + 4 * j,
                   Ww + (size_t)(m0 + m) * 128 + 4 * j);
    }
    CP_COMMIT();

    // X tile: pairs along k, [u][n] layout (PRMT pack, STS.64)
#pragma unroll
    for (int r = 0; r < 16; r++) {
        int p = tid + 256 * r;          // 0..4095
        int u = p >> 5, tp = p & 31;
        uint32_t x0 = Xw[(size_t)(2 * u)     * (NTOK / 2) + (n0 >> 1) + tp];
        uint32_t x1 = Xw[(size_t)(2 * u + 1) * (NTOK / 2) + (n0 >> 1) + tp];
        *reinterpret_cast<uint2*>(sX + u * GX_STRIDE + 2 * tp) =
            make_uint2(prmt(x0, x1, 0x5410), prmt(x0, x1, 0x7632));
    }
    CP_WAIT0();
    __syncthreads();

    float acc[4][4] = {};
#pragma unroll
    for (int ks = 0; ks < 16; ks++) {
        const int ub = 8 * ks + qc;
        uint32_t a0 = sW[(r0 + qr) * GW_STRIDE + ub];
        uint32_t a1 = sW[(r0 + qr + 8) * GW_STRIDE + ub];
        uint32_t a2 = sW[(r0 + qr) * GW_STRIDE + ub + 4];
        uint32_t a3 = sW[(r0 + qr + 8) * GW_STRIDE + ub + 4];
#pragma unroll
        for (int nt = 0; nt < 4; nt++) {
            int col = wk * 32 + nt * 8 + qr;
            uint32_t b0 = sX[ub * GX_STRIDE + col];
            uint32_t b1 = sX[(ub + 4) * GX_STRIDE + col];
            MMA_BF16(acc[nt], a0, a1, a2, a3, b0, b1);
        }
    }

    // epilogue
    if (out_bf16) {
        uint32_t* Yb = (uint32_t*)Y + (size_t)b * (size_t)M * (NTOK / 2);
#pragma unroll
        for (int nt = 0; nt < 4; nt++) {
            int col = wk * 32 + nt * 8 + 2 * qc;        // even
            int m = m0 + r0 + qr;
            __nv_bfloat162 lo = {__float2bfloat16(acc[nt][0]),
                                 __float2bfloat16(acc[nt][1])};
            __nv_bfloat162 hi = {__float2bfloat16(acc[nt][2]),
                                 __float2bfloat16(acc[nt][3])};
            Yb[(size_t)m * (NTOK / 2) + ((n0 + col) >> 1)]       = *(uint32_t*)&lo;
            Yb[(size_t)(m + 8) * (NTOK / 2) + ((n0 + col) >> 1)] = *(uint32_t*)&hi;
        }
    } else {
        float* Yb = (float*)Y + (size_t)b * (size_t)M * NTOK;
        const float* Rb = resid + (size_t)b * (size_t)M * NTOK;
#pragma unroll
        for (int nt = 0; nt < 4; nt++) {
            int col = n0 + wk * 32 + nt * 8 + 2 * qc;
            int m = m0 + r0 + qr;
            float bi0 = bias ? bias[m] : 0.f;
            float bi1 = bias ? bias[m + 8] : 0.f;
            float2 r0v = *reinterpret_cast<const float2*>(&Rb[(size_t)m * NTOK + col]);
            float2 r1v = *reinterpret_cast<const float2*>(&Rb[(size_t)(m + 8) * NTOK + col]);
            float2 v0 = {acc[nt][0] + bi0 + r0v.x, acc[nt][1] + bi0 + r0v.y};
            float2 v1 = {acc[nt][2] + bi1 + r1v.x, acc[nt][3] + bi1 + r1v.y};
            *reinterpret_cast<float2*>(&Yb[(size_t)m * NTOK + col]) = v0;
            *reinterpret_cast<float2*>(&Yb[(size_t)(m + 8) * NTOK + col]) = v1;
        }
    }
}

// ---------------------------------------------------------------------------
// 3) Fused flash attention, bf16 m16n8k16 mma, double-buffered K/V.
//    (unchanged from R13 except bf16 epilogue)
// ---------------------------------------------------------------------------
#define TPW 72
#define VPW 36
#define PPW 36
#define SPW 68

#define OFF_Q   0
#define OFF_K   (OFF_Q + 128 * TPW)
#define OFF_V   (OFF_K + 2 * 128 * TPW)
#define OFF_S   (OFF_V + 2 * 256 * VPW)
#define OFF_P   (OFF_S + 64 * SPW)
#define OFF_MX  (OFF_P + 64 * PPW)
#define OFF_L   (OFF_MX + 64)
#define OFF_AL  (OFF_L + 64)
#define SMEM_WORDS (OFF_AL + 64)
#define ATTN_SMEM (SMEM_WORDS * 4)             // 211712 B

__global__ void __launch_bounds__(256, 1) attn_kernel(
    const __nv_bfloat16* __restrict__ qkv, __nv_bfloat16* __restrict__ att)
{
    extern __shared__ uint32_t sm[];
    uint32_t* sQ = sm + OFF_Q;
    uint32_t* sK = sm + OFF_K;
    uint32_t* sV = sm + OFF_V;
    float*    sSf = (float*)(sm + OFF_S);
    uint32_t* sPw = sm + OFF_P;
    __nv_bfloat16* sPh = (__nv_bfloat16*)sPw;
    float* sMx = (float*)(sm + OFF_MX);
    float* sL  = (float*)(sm + OFF_L);
    float* sAl = (float*)(sm + OFF_AL);

    const int tid  = threadIdx.x;
    const int lane = tid & 31;
    const int warp = tid >> 5;
    const int wq = warp >> 1;
    const int wk = warp & 1;
    const int r0 = wq * 16;
    const int qr = lane >> 2;
    const int qc = lane & 3;

    const int b  = blockIdx.y;
    const int n0 = blockIdx.x * 64;
    const uint32_t* qb32 = (const uint32_t*)(qkv + (size_t)b * 3 * CH * NTOK);
    const uint32_t* kb32 = qb32 + (size_t)CH * NTOK / 2;
    const char*     vbytes = (const char*)(kb32 + (size_t)CH * NTOK / 2);

    if (tid < 64) { sMx[tid] = -3.0e38f; sL[tid] = 0.f; }

    // prologue: Q (pair layout), K tile 0, V tile 0
#pragma unroll
    for (int r = 0; r < 16; r++) {
        int p = tid + 256 * r, u = p >> 5, tp = p & 31;
        uint32_t x0 = qb32[(size_t)(2 * u)     * (NTOK / 2) + (n0 >> 1) + tp];
        uint32_t x1 = qb32[(size_t)(2 * u + 1) * (NTOK / 2) + (n0 >> 1) + tp];
        *reinterpret_cast<uint2*>(sQ + u * TPW + 2 * tp) =
            make_uint2(prmt(x0, x1, 0x5410), prmt(x0, x1, 0x7632));
    }
#pragma unroll
    for (int r = 0; r < 16; r++) {
        int p = tid + 256 * r, u = p >> 5, tp = p & 31;
        uint32_t x0 = kb32[(size_t)(2 * u)     * (NTOK / 2) + tp];
        uint32_t x1 = kb32[(size_t)(2 * u + 1) * (NTOK / 2) + tp];
        *reinterpret_cast<uint2*>(sK + u * TPW + 2 * tp) =
            make_uint2(prmt(x0, x1, 0x5410), prmt(x0, x1, 0x7632));
    }
#pragma unroll
    for (int i = 0; i < 8; i++) {
        int q = tid + 256 * i, chan = q >> 3, ch = q & 7;
        cp_async16(sV + chan * VPW + ch * 4,
                   vbytes + ((size_t)chan * NTOK) * 2 + ch * 16);
    }
    CP_COMMIT();
    CP_WAIT0();
    __syncthreads();

    float o[16][4];
#pragma unroll
    for (int nt = 0; nt < 16; nt++)
#pragma unroll
        for (int j = 0; j < 4; j++) o[nt][j] = 0.f;

    for (int kt = 0; kt < NTOK / 64; kt++) {
        const int cur = kt & 1, nxt = cur ^ 1;
        const int m0n = ((kt + 1) & 63) * 64;
        uint32_t* sKc = sK + cur * (128 * TPW);
        uint32_t* sKn = sK + nxt * (128 * TPW);
        uint32_t* sVc = sV + cur * (256 * VPW);
        uint32_t* sVn = sV + nxt * (256 * VPW);

#pragma unroll
        for (int i = 0; i < 8; i++) {
            int q = tid + 256 * i, chan = q >> 3, ch = q & 7;
            cp_async16(sVn + chan * VPW + ch * 4,
                       vbytes + ((size_t)chan * NTOK + m0n) * 2 + ch * 16);
        }
        CP_COMMIT();

        uint32_t kr0[16], kr1[16];
#pragma unroll
        for (int r = 0; r < 16; r++) {
            int p = tid + 256 * r, u = p >> 5, tp = p & 31;
            kr0[r] = kb32[(size_t)(2 * u)     * (NTOK / 2) + (m0n >> 1) + tp];
            kr1[r] = kb32[(size_t)(2 * u + 1) * (NTOK / 2) + (m0n >> 1) + tp];
        }

        // S = Q K^T
        float acc[4][4] = {};
#pragma unroll
        for (int ks = 0; ks < 16; ks++) {
            const int ub = 8 * ks + qc;
            uint32_t a0 = sQ[ub * TPW + r0 + qr];
            uint32_t a1 = sQ[ub * TPW + r0 + qr + 8];
            uint32_t a2 = sQ[(ub + 4) * TPW + r0 + qr];
            uint32_t a3 = sQ[(ub + 4) * TPW + r0 + qr + 8];
#pragma unroll
            for (int nt = 0; nt < 4; nt++) {
                int col = wk * 32 + nt * 8 + qr;
                uint32_t b0 = sKc[ub * TPW + col];
                uint32_t b1 = sKc[(ub + 4) * TPW + col];
                MMA_BF16(acc[nt], a0, a1, a2, a3, b0, b1);
            }
        }
#pragma unroll
        for (int nt = 0; nt < 4; nt++) {
            int colb = wk * 32 + nt * 8 + 2 * qc;
            int rr = r0 + qr;
            sSf[rr * SPW + colb]           = acc[nt][0] * SCALE;
            sSf[rr * SPW + colb + 1]       = acc[nt][1] * SCALE;
            sSf[(rr + 8) * SPW + colb]     = acc[nt][2] * SCALE;
            sSf[(rr + 8) * SPW + colb + 1] = acc[nt][3] * SCALE;
        }
        asm volatile("bar.sync %0, 64;" :: "r"(1 + wq) : "memory");

        // online softmax
        {
            int row = tid >> 2, sub = tid & 3;
            float mold = sMx[row];
            float mx = mold;
#pragma unroll
            for (int j = sub; j < 64; j += 4) mx = fmaxf(mx, sSf[row * SPW + j]);
            mx = fmaxf(mx, __shfl_xor_sync(0xffffffffu, mx, 1));
            mx = fmaxf(mx, __shfl_xor_sync(0xffffffffu, mx, 2));
            float lsum = 0.f;
#pragma unroll
            for (int j = sub; j < 64; j += 4) {
                float pv = __expf(sSf[row * SPW + j] - mx);
                sPh[row * (PPW * 2) + j] = __float2bfloat16(pv);
                lsum += pv;
            }
            lsum += __shfl_xor_sync(0xffffffffu, lsum, 1);
            lsum += __shfl_xor_sync(0xffffffffu, lsum, 2);
            if (sub == 0) {
                float alpha = __expf(mold - mx);
                sAl[row] = alpha;
                sMx[row] = mx;
                sL[row]  = sL[row] * alpha + lsum;
            }
        }
        asm volatile("bar.sync %0, 64;" :: "r"(1 + wq) : "memory");

        // store K(next)
#pragma unroll
        for (int r = 0; r < 16; r++) {
            int p = tid + 256 * r, u = p >> 5, tp = p & 31;
            *reinterpret_cast<uint2*>(sKn + u * TPW + 2 * tp) =
                make_uint2(prmt(kr0[r], kr1[r], 0x5410),
                           prmt(kr0[r], kr1[r], 0x7632));
        }

        // rescale O, then O += P * V
        float aLo = sAl[r0 + qr];
        float aHi = sAl[r0 + qr + 8];
#pragma unroll
        for (int nt = 0; nt < 16; nt++) {
            o[nt][0] *= aLo; o[nt][1] *= aLo;
            o[nt][2] *= aHi; o[nt][3] *= aHi;
        }
#pragma unroll
        for (int ks = 0; ks < 4; ks++) {
            const int ub = 8 * ks + qc;
            uint32_t a0 = sPw[(r0 + qr) * PPW + ub];
            uint32_t a1 = sPw[(r0 + qr + 8) * PPW + ub];
            uint32_t a2 = sPw[(r0 + qr) * PPW + ub + 4];
            uint32_t a3 = sPw[(r0 + qr + 8) * PPW + ub + 4];
#pragma unroll
            for (int nt = 0; nt < 16; nt++) {
                int chan = wk * 128 + nt * 8 + qr;
                uint32_t b0 = sVc[chan * VPW + ub];
                uint32_t b1 = sVc[chan * VPW + ub + 4];
                MMA_BF16(o[nt], a0, a1, a2, a3, b0, b1);
            }
        }
        CP_WAIT0();
        __syncthreads();
    }

    // epilogue: divide by l, write bf16 att[b, c, n]
    const float lLo = 1.f / sL[r0 + qr];
    const float lHi = 1.f / sL[r0 + qr + 8];
    __nv_bfloat16* ab = att + (size_t)b * CH * NTOK;
    const int nLo = n0 + r0 + qr;
    const int nHi = nLo + 8;
#pragma unroll
    for (int nt = 0; nt < 16; nt++) {
        int c = wk * 128 + nt * 8 + 2 * qc;
        ab[(size_t)c * NTOK + nLo]       = __float2bfloat16(o[nt][0] * lLo);
        ab[(size_t)(c + 1) * NTOK + nLo] = __float2bfloat16(o[nt][1] * lLo);
        ab[(size_t)c * NTOK + nHi]       = __float2bfloat16(o[nt][2] * lHi);
        ab[(size_t)(c + 1) * NTOK + nHi] = __float2bfloat16(o[nt][3] * lHi);
    }
}

// ---------------------------------------------------------------------------
// launch
// ---------------------------------------------------------------------------
extern "C" void kernel_launch(void* const* d_in, const int* in_sizes, int n_in,
                              void* d_out, int out_size)
{
    const float* x      = (const float*)d_in[0];
    const float* gamma  = (const float*)d_in[1];
    const float* beta   = (const float*)d_in[2];
    const float* w_qkv  = (const float*)d_in[3];
    const float* w_proj = (const float*)d_in[4];
    const float* b_proj = (const float*)d_in[5];
    float* out = (float*)d_out;

    __nv_bfloat16 *xn, *qkv, *att, *wqh, *wph;
    cudaGetSymbolAddress((void**)&xn,  g_xn);
    cudaGetSymbolAddress((void**)&qkv, g_qkv);
    cudaGetSymbolAddress((void**)&att, g_att);
    cudaGetSymbolAddress((void**)&wqh, g_wqkv_h);
    cudaGetSymbolAddress((void**)&wph, g_wproj_h);

    // 0) convert weights to bf16
    cvt_w_kernel<<<192, 256>>>(w_qkv, w_proj, wqh, wph);

    // 1) GroupNorm -> bf16
    gn_kernel<<<BATCH * GROUPS, 256>>>(x, gamma, beta, xn);

    // 2) QKV = W_qkv @ xn  -> bf16  (mma)
    cudaFuncSetAttribute(mma_gemm_kernel,
                         cudaFuncAttributeMaxDynamicSharedMemorySize, GEMM_SMEM);
    mma_gemm_kernel<<<dim3(NTOK / 64, (3 * CH) / 64, BATCH), 256, GEMM_SMEM>>>(
        wqh, xn, nullptr, nullptr, qkv, 3 * CH, 1);

    // 3) fused flash attention (bf16 mma, pipelined) -> bf16 att
    cudaFuncSetAttribute(attn_kernel,
                         cudaFuncAttributeMaxDynamicSharedMemorySize, ATTN_SMEM);
    attn_kernel<<<dim3(NTOK / 64, BATCH), 256, ATTN_SMEM>>>(qkv, att);

    // 4) out = x + W_proj @ att + b_proj  (mma, fp32 out)
    mma_gemm_kernel<<<dim3(NTOK / 64, CH / 64, BATCH), 256, GEMM_SMEM>>>(
        wph, att, b_proj, x, out, CH, 0);
}

// round 16
// speedup vs baseline: 1.5755x; 1.1734x over previous
#include <cuda_runtime.h>
#include <cuda_bf16.h>
#include <cstdint>

// Problem constants
#define BATCH 4
#define CH    256
#define NTOK  4096
#define GROUPS 8
#define CPG   (CH / GROUPS)
#define EPSV  1e-5f
#define SCALE 0.0625f         // CH^-0.5

// ---------------------------------------------------------------------------
// Scratch (no cudaMalloc allowed -> __device__ globals)
// ---------------------------------------------------------------------------
__device__ __nv_bfloat16 g_xn [(size_t)BATCH * CH * NTOK];      // 8 MB
__device__ __nv_bfloat16 g_qkv[(size_t)BATCH * 3 * CH * NTOK];  // 25 MB
__device__ __nv_bfloat16 g_att[(size_t)BATCH * CH * NTOK];      // 8 MB
__device__ __nv_bfloat16 g_wqkv_h[3 * CH * CH];                 // 384 KB
__device__ __nv_bfloat16 g_wproj_h[CH * CH];                    // 128 KB

// ---------------------------------------------------------------------------
// helpers
// ---------------------------------------------------------------------------
__device__ __forceinline__ uint32_t prmt(uint32_t a, uint32_t b, uint32_t sel) {
    uint32_t d;
    asm("prmt.b32 %0, %1, %2, %3;" : "=r"(d) : "r"(a), "r"(b), "r"(sel));
    return d;
}

__device__ __forceinline__ void cp_async16(void* smem_dst, const void* gsrc) {
    uint32_t s = (uint32_t)__cvta_generic_to_shared(smem_dst);
    asm volatile("cp.async.cg.shared.global [%0], [%1], 16;" :: "r"(s), "l"(gsrc));
}
#define CP_COMMIT() asm volatile("cp.async.commit_group;" ::: "memory")
#define CP_WAIT0()  asm volatile("cp.async.wait_group 0;"  ::: "memory")

#define MMA_BF16(d, a0, a1, a2, a3, b0, b1)                                   \
    asm volatile(                                                             \
        "mma.sync.aligned.m16n8k16.row.col.f32.bf16.bf16.f32 "                \
        "{%0,%1,%2,%3}, {%4,%5,%6,%7}, {%8,%9}, {%0,%1,%2,%3};"               \
        : "+f"((d)[0]), "+f"((d)[1]), "+f"((d)[2]), "+f"((d)[3])              \
        : "r"(a0), "r"(a1), "r"(a2), "r"(a3), "r"(b0), "r"(b1))

// ---------------------------------------------------------------------------
// 0) weight fp32 -> bf16 conversion
// ---------------------------------------------------------------------------
__global__ void __launch_bounds__(256) cvt_w_kernel(
    const float* __restrict__ wq, const float* __restrict__ wp,
    __nv_bfloat16* __restrict__ wqh, __nv_bfloat16* __restrict__ wph)
{
    const int stride = gridDim.x * 256;
    for (int p = blockIdx.x * 256 + threadIdx.x; p < 3 * CH * CH; p += stride)
        wqh[p] = __float2bfloat16(wq[p]);
    for (int p = blockIdx.x * 256 + threadIdx.x; p < CH * CH; p += stride)
        wph[p] = __float2bfloat16(wp[p]);
}

// ---------------------------------------------------------------------------
// 1) GroupNorm: one CTA per (batch, group). bf16 output.
// ---------------------------------------------------------------------------
__global__ void __launch_bounds__(256) gn_kernel(
    const float* __restrict__ x, const float* __restrict__ gamma,
    const float* __restrict__ beta, __nv_bfloat16* __restrict__ xn)
{
    const int b = blockIdx.x >> 3;
    const int g = blockIdx.x & 7;
    const size_t base = ((size_t)b * CH + (size_t)g * CPG) * NTOK;
    const float* xp = x + base;
    const int CNT = CPG * NTOK;

    float s = 0.f, ss = 0.f;
    for (int i = threadIdx.x; i < CNT; i += 256) {
        float v = xp[i];
        s += v; ss += v * v;
    }
#pragma unroll
    for (int off = 16; off; off >>= 1) {
        s  += __shfl_down_sync(0xffffffffu, s,  off);
        ss += __shfl_down_sync(0xffffffffu, ss, off);
    }
    __shared__ float rs[8], rss[8], stats[2];
    const int w = threadIdx.x >> 5, lane = threadIdx.x & 31;
    if (lane == 0) { rs[w] = s; rss[w] = ss; }
    __syncthreads();
    if (threadIdx.x == 0) {
        float S = 0.f, SS = 0.f;
#pragma unroll
        for (int i = 0; i < 8; i++) { S += rs[i]; SS += rss[i]; }
        float mu  = S * (1.f / (float)CNT);
        float var = SS * (1.f / (float)CNT) - mu * mu;
        stats[0] = mu;
        stats[1] = rsqrtf(var + EPSV);
    }
    __syncthreads();
    const float mu = stats[0], rstd = stats[1];
    for (int i = threadIdx.x; i < CNT; i += 256) {
        int c = g * CPG + (i >> 12);
        xn[base + i] = __float2bfloat16((xp[i] - mu) * rstd * gamma[c] + beta[c]);
    }
}

// ---------------------------------------------------------------------------
// 2/4) bf16 mma GEMM (unchanged from R15, ~measured 30-40us each pass)
// ---------------------------------------------------------------------------
#define GW_STRIDE 132
#define GX_STRIDE 72
#define GEMM_SMEM ((64 * GW_STRIDE + 128 * GX_STRIDE) * 4)   // 70656 B

__global__ void __launch_bounds__(256, 2) mma_gemm_kernel(
    const __nv_bfloat16* __restrict__ Wh,
    const __nv_bfloat16* __restrict__ X,
    const float* __restrict__ bias,
    const float* __restrict__ resid,
    void* __restrict__ Y, int M, int out_bf16)
{
    extern __shared__ uint32_t smg[];
    uint32_t* sW = smg;
    uint32_t* sX = smg + 64 * GW_STRIDE;

    const int b  = blockIdx.z;
    const int n0 = blockIdx.x * 64;
    const int m0 = blockIdx.y * 64;
    const int tid = threadIdx.x, lane = tid & 31, warp = tid >> 5;
    const int wq = warp >> 1, wk = warp & 1;
    const int r0 = wq * 16, qr = lane >> 2, qc = lane & 3;

    const uint32_t* Ww = (const uint32_t*)Wh;
    const uint32_t* Xw = (const uint32_t*)(X + (size_t)b * CH * NTOK);

#pragma unroll
    for (int i = 0; i < 8; i++) {
        int p = tid + 256 * i;
        int m = p >> 5, j = p & 31;
        cp_async16(sW + m * GW_STRIDE + 4 * j,
                   Ww + (size_t)(m0 + m) * 128 + 4 * j);
    }
    CP_COMMIT();

#pragma unroll
    for (int r = 0; r < 16; r++) {
        int p = tid + 256 * r;
        int u = p >> 5, tp = p & 31;
        uint32_t x0 = Xw[(size_t)(2 * u)     * (NTOK / 2) + (n0 >> 1) + tp];
        uint32_t x1 = Xw[(size_t)(2 * u + 1) * (NTOK / 2) + (n0 >> 1) + tp];
        *reinterpret_cast<uint2*>(sX + u * GX_STRIDE + 2 * tp) =
            make_uint2(prmt(x0, x1, 0x5410), prmt(x0, x1, 0x7632));
    }
    CP_WAIT0();
    __syncthreads();

    float acc[4][4] = {};
#pragma unroll
    for (int ks = 0; ks < 16; ks++) {
        const int ub = 8 * ks + qc;
        uint32_t a0 = sW[(r0 + qr) * GW_STRIDE + ub];
        uint32_t a1 = sW[(r0 + qr + 8) * GW_STRIDE + ub];
        uint32_t a2 = sW[(r0 + qr) * GW_STRIDE + ub + 4];
        uint32_t a3 = sW[(r0 + qr + 8) * GW_STRIDE + ub + 4];
#pragma unroll
        for (int nt = 0; nt < 4; nt++) {
            int col = wk * 32 + nt * 8 + qr;
            uint32_t b0 = sX[ub * GX_STRIDE + col];
            uint32_t b1 = sX[(ub + 4) * GX_STRIDE + col];
            MMA_BF16(acc[nt], a0, a1, a2, a3, b0, b1);
        }
    }

    if (out_bf16) {
        uint32_t* Yb = (uint32_t*)Y + (size_t)b * (size_t)M * (NTOK / 2);
#pragma unroll
        for (int nt = 0; nt < 4; nt++) {
            int col = wk * 32 + nt * 8 + 2 * qc;
            int m = m0 + r0 + qr;
            __nv_bfloat162 lo = {__float2bfloat16(acc[nt][0]),
                                 __float2bfloat16(acc[nt][1])};
            __nv_bfloat162 hi = {__float2bfloat16(acc[nt][2]),
                                 __float2bfloat16(acc[nt][3])};
            Yb[(size_t)m * (NTOK / 2) + ((n0 + col) >> 1)]       = *(uint32_t*)&lo;
            Yb[(size_t)(m + 8) * (NTOK / 2) + ((n0 + col) >> 1)] = *(uint32_t*)&hi;
        }
    } else {
        float* Yb = (float*)Y + (size_t)b * (size_t)M * NTOK;
        const float* Rb = resid + (size_t)b * (size_t)M * NTOK;
#pragma unroll
        for (int nt = 0; nt < 4; nt++) {
            int col = n0 + wk * 32 + nt * 8 + 2 * qc;
            int m = m0 + r0 + qr;
            float bi0 = bias ? bias[m] : 0.f;
            float bi1 = bias ? bias[m + 8] : 0.f;
            float2 r0v = *reinterpret_cast<const float2*>(&Rb[(size_t)m * NTOK + col]);
            float2 r1v = *reinterpret_cast<const float2*>(&Rb[(size_t)(m + 8) * NTOK + col]);
            float2 v0 = {acc[nt][0] + bi0 + r0v.x, acc[nt][1] + bi0 + r0v.y};
            float2 v1 = {acc[nt][2] + bi1 + r1v.x, acc[nt][3] + bi1 + r1v.y};
            *reinterpret_cast<float2*>(&Yb[(size_t)m * NTOK + col]) = v0;
            *reinterpret_cast<float2*>(&Yb[(size_t)(m + 8) * NTOK + col]) = v1;
        }
    }
}

// ---------------------------------------------------------------------------
// 3) Fused flash attention, Bq=128, Bk=64. Grid (32, 4) = 128 CTAs, 8 warps.
//    Warp (wq=warp>>1, wk=warp&1):
//      S : rows 32*wq..+31 (2 m-blocks), keys 32*wk..+31     -> acc[2][4][4]
//      PV: rows 32*wq..+31,             chans 128*wk..+127   -> o[2][16][4]
//    smem: Q [128u][QS=136] pair layout; K single buf [128u][72];
//          V dbl buf [256c][36]; S fp32 [128][68] with bf16 P overlaid in place.
// ---------------------------------------------------------------------------
#define QS  136
#define TPW 72
#define VPW 36
#define SPW 68

#define OFF_Q   0
#define OFF_K   (OFF_Q + 128 * QS)            // 17408
#define OFF_V   (OFF_K + 128 * TPW)           // 26624
#define OFF_S   (OFF_V + 2 * 256 * VPW)       // 45056
#define OFF_MX  (OFF_S + 128 * SPW)           // 53760
#define OFF_L   (OFF_MX + 128)
#define OFF_AL  (OFF_L + 128)
#define SMEM_WORDS (OFF_AL + 128)             // 54144
#define ATTN_SMEM (SMEM_WORDS * 4)            // 216576 B

__global__ void __launch_bounds__(256, 1) attn_kernel(
    const __nv_bfloat16* __restrict__ qkv, __nv_bfloat16* __restrict__ att)
{
    extern __shared__ uint32_t sm[];
    uint32_t* sQ = sm + OFF_Q;
    uint32_t* sK = sm + OFF_K;
    uint32_t* sV = sm + OFF_V;
    float*    sSf = (float*)(sm + OFF_S);
    uint32_t* sPw = sm + OFF_S;                  // P overlays S (in-place)
    __nv_bfloat16* sPh = (__nv_bfloat16*)sPw;
    float* sMx = (float*)(sm + OFF_MX);
    float* sL  = (float*)(sm + OFF_L);
    float* sAl = (float*)(sm + OFF_AL);

    const int tid  = threadIdx.x;
    const int lane = tid & 31;
    const int warp = tid >> 5;
    const int wq = warp >> 1;     // 0..3 : 32-row q block
    const int wk = warp & 1;      // 0..1 : key half (S) / chan half (PV)
    const int r0 = wq * 32;
    const int qr = lane >> 2;     // 0..7
    const int qc = lane & 3;      // 0..3

    const int b  = blockIdx.y;
    const int n0 = blockIdx.x * 128;
    const uint32_t* qb32 = (const uint32_t*)(qkv + (size_t)b * 3 * CH * NTOK);
    const uint32_t* kb32 = qb32 + (size_t)CH * NTOK / 2;
    const char*     vbytes = (const char*)(kb32 + (size_t)CH * NTOK / 2);

    if (tid < 128) { sMx[tid] = -3.0e38f; sL[tid] = 0.f; }

    // ---- prologue: Q (pair layout, 128 tokens), K tile 0, V tile 0 ----
#pragma unroll
    for (int r = 0; r < 32; r++) {
        int p = tid + 256 * r;          // 0..8191
        int u = p >> 6, tp = p & 63;    // u: chan pair, tp: token pair
        uint32_t x0 = qb32[(size_t)(2 * u)     * (NTOK / 2) + (n0 >> 1) + tp];
        uint32_t x1 = qb32[(size_t)(2 * u + 1) * (NTOK / 2) + (n0 >> 1) + tp];
        *reinterpret_cast<uint2*>(sQ + u * QS + 2 * tp) =
            make_uint2(prmt(x0, x1, 0x5410), prmt(x0, x1, 0x7632));
    }
#pragma unroll
    for (int r = 0; r < 16; r++) {
        int p = tid + 256 * r, u = p >> 5, tp = p & 31;
        uint32_t x0 = kb32[(size_t)(2 * u)     * (NTOK / 2) + tp];
        uint32_t x1 = kb32[(size_t)(2 * u + 1) * (NTOK / 2) + tp];
        *reinterpret_cast<uint2*>(sK + u * TPW + 2 * tp) =
            make_uint2(prmt(x0, x1, 0x5410), prmt(x0, x1, 0x7632));
    }
#pragma unroll
    for (int i = 0; i < 8; i++) {
        int q = tid + 256 * i, chan = q >> 3, ch = q & 7;
        cp_async16(sV + chan * VPW + ch * 4,
                   vbytes + ((size_t)chan * NTOK) * 2 + ch * 16);
    }
    CP_COMMIT();
    CP_WAIT0();
    __syncthreads();

    float o[2][16][4];
#pragma unroll
    for (int m = 0; m < 2; m++)
#pragma unroll
        for (int nt = 0; nt < 16; nt++)
#pragma unroll
            for (int j = 0; j < 4; j++) o[m][nt][j] = 0.f;

    for (int kt = 0; kt < NTOK / 64; kt++) {
        const int cur = kt & 1, nxt = cur ^ 1;
        const int m0n = ((kt + 1) & 63) * 64;       // next key tile (wraps)
        uint32_t* sVc = sV + cur * (256 * VPW);
        uint32_t* sVn = sV + nxt * (256 * VPW);

        // async V prefetch (next tile)
#pragma unroll
        for (int i = 0; i < 8; i++) {
            int q = tid + 256 * i, chan = q >> 3, ch = q & 7;
            cp_async16(sVn + chan * VPW + ch * 4,
                       vbytes + ((size_t)chan * NTOK + m0n) * 2 + ch * 16);
        }
        CP_COMMIT();

        // K prefetch (next tile) into regs; STS after the post-S barrier
        uint32_t kr0[16], kr1[16];
#pragma unroll
        for (int r = 0; r < 16; r++) {
            int p = tid + 256 * r, u = p >> 5, tp = p & 31;
            kr0[r] = kb32[(size_t)(2 * u)     * (NTOK / 2) + (m0n >> 1) + tp];
            kr1[r] = kb32[(size_t)(2 * u + 1) * (NTOK / 2) + (m0n >> 1) + tp];
        }

        // ---- S = Q K^T : 32 rows x 32 keys per warp ----
        float acc[2][4][4] = {};
#pragma unroll
        for (int ks = 0; ks < 16; ks++) {
            const int ub = 8 * ks + qc;
            uint32_t a00 = sQ[ub * QS + r0 + qr];
            uint32_t a01 = sQ[ub * QS + r0 + qr + 8];
            uint32_t a02 = sQ[(ub + 4) * QS + r0 + qr];
            uint32_t a03 = sQ[(ub + 4) * QS + r0 + qr + 8];
            uint32_t a10 = sQ[ub * QS + r0 + 16 + qr];
            uint32_t a11 = sQ[ub * QS + r0 + 16 + qr + 8];
            uint32_t a12 = sQ[(ub + 4) * QS + r0 + 16 + qr];
            uint32_t a13 = sQ[(ub + 4) * QS + r0 + 16 + qr + 8];
#pragma unroll
            for (int nt = 0; nt < 4; nt++) {
                int col = wk * 32 + nt * 8 + qr;
                uint32_t b0 = sK[ub * TPW + col];
                uint32_t b1 = sK[(ub + 4) * TPW + col];
                MMA_BF16(acc[0][nt], a00, a01, a02, a03, b0, b1);
                MMA_BF16(acc[1][nt], a10, a11, a12, a13, b0, b1);
            }
        }
#pragma unroll
        for (int m = 0; m < 2; m++)
#pragma unroll
            for (int nt = 0; nt < 4; nt++) {
                int rr = r0 + 16 * m + qr;
                int colb = wk * 32 + nt * 8 + 2 * qc;
                float2 v0 = {acc[m][nt][0] * SCALE, acc[m][nt][1] * SCALE};
                float2 v1 = {acc[m][nt][2] * SCALE, acc[m][nt][3] * SCALE};
                *reinterpret_cast<float2*>(&sSf[rr * SPW + colb])       = v0;
                *reinterpret_cast<float2*>(&sSf[(rr + 8) * SPW + colb]) = v1;
            }
        __syncthreads();   // S complete; K(cur) fully consumed

        // ---- store K(next) into the single K buffer ----
#pragma unroll
        for (int r = 0; r < 16; r++) {
            int p = tid + 256 * r, u = p >> 5, tp = p & 31;
            *reinterpret_cast<uint2*>(sK + u * TPW + 2 * tp) =
                make_uint2(prmt(kr0[r], kr1[r], 0x5410),
                           prmt(kr0[r], kr1[r], 0x7632));
        }

        // ---- online softmax: 2 lanes per row, P written in place over S ----
        {
            int row = tid >> 1, sub = tid & 1;
            float mold = sMx[row];
            float mx = mold;
#pragma unroll
            for (int j = sub; j < 64; j += 2) mx = fmaxf(mx, sSf[row * SPW + j]);
            mx = fmaxf(mx, __shfl_xor_sync(0xffffffffu, mx, 1));
            float lsum = 0.f;
#pragma unroll
            for (int j = sub; j < 64; j += 2) {
                float pv = __expf(sSf[row * SPW + j] - mx);
                sPh[row * (SPW * 2) + j] = __float2bfloat16(pv);
                lsum += pv;
            }
            lsum += __shfl_xor_sync(0xffffffffu, lsum, 1);
            if (sub == 0) {
                float alpha = __expf(mold - mx);
                sAl[row] = alpha;
                sMx[row] = mx;
                sL[row]  = sL[row] * alpha + lsum;
            }
        }
        __syncthreads();   // P + stats + K(next) visible

        // ---- rescale O, then O += P * V : 32 rows x 128 chans per warp ----
        float aL0 = sAl[r0 + qr],      aH0 = sAl[r0 + qr + 8];
        float aL1 = sAl[r0 + 16 + qr], aH1 = sAl[r0 + 16 + qr + 8];
#pragma unroll
        for (int nt = 0; nt < 16; nt++) {
            o[0][nt][0] *= aL0; o[0][nt][1] *= aL0;
            o[0][nt][2] *= aH0; o[0][nt][3] *= aH0;
            o[1][nt][0] *= aL1; o[1][nt][1] *= aL1;
            o[1][nt][2] *= aH1; o[1][nt][3] *= aH1;
        }
#pragma unroll
        for (int ks = 0; ks < 4; ks++) {
            const int ub = 8 * ks + qc;
            uint32_t p00 = sPw[(r0 + qr) * SPW + ub];
            uint32_t p01 = sPw[(r0 + qr + 8) * SPW + ub];
            uint32_t p02 = sPw[(r0 + qr) * SPW + ub + 4];
            uint32_t p03 = sPw[(r0 + qr + 8) * SPW + ub + 4];
            uint32_t p10 = sPw[(r0 + 16 + qr) * SPW + ub];
            uint32_t p11 = sPw[(r0 + 16 + qr + 8) * SPW + ub];
            uint32_t p12 = sPw[(r0 + 16 + qr) * SPW + ub + 4];
            uint32_t p13 = sPw[(r0 + 16 + qr + 8) * SPW + ub + 4];
#pragma unroll
            for (int nt = 0; nt < 16; nt++) {
                int chan = wk * 128 + nt * 8 + qr;
                uint32_t b0 = sVc[chan * VPW + ub];
                uint32_t b1 = sVc[chan * VPW + ub + 4];
                MMA_BF16(o[0][nt], p00, p01, p02, p03, b0, b1);
                MMA_BF16(o[1][nt], p10, p11, p12, p13, b0, b1);
            }
        }
        CP_WAIT0();
        __syncthreads();   // V(next) landed; S region free for next tile
    }

    // ---- epilogue: divide by l, write bf16 att[b, c, n] ----
    __nv_bfloat16* ab = att + (size_t)b * CH * NTOK;
#pragma unroll
    for (int m = 0; m < 2; m++) {
        const float lLo = 1.f / sL[r0 + 16 * m + qr];
        const float lHi = 1.f / sL[r0 + 16 * m + qr + 8];
        const int nLo = n0 + r0 + 16 * m + qr;
        const int nHi = nLo + 8;
#pragma unroll
        for (int nt = 0; nt < 16; nt++) {
            int c = wk * 128 + nt * 8 + 2 * qc;
            ab[(size_t)c * NTOK + nLo]       = __float2bfloat16(o[m][nt][0] * lLo);
            ab[(size_t)(c + 1) * NTOK + nLo] = __float2bfloat16(o[m][nt][1] * lLo);
            ab[(size_t)c * NTOK + nHi]       = __float2bfloat16(o[m][nt][2] * lHi);
            ab[(size_t)(c + 1) * NTOK + nHi] = __float2bfloat16(o[m][nt][3] * lHi);
        }
    }
}

// ---------------------------------------------------------------------------
// launch
// ---------------------------------------------------------------------------
extern "C" void kernel_launch(void* const* d_in, const int* in_sizes, int n_in,
                              void* d_out, int out_size)
{
    const float* x      = (const float*)d_in[0];
    const float* gamma  = (const float*)d_in[1];
    const float* beta   = (const float*)d_in[2];
    const float* w_qkv  = (const float*)d_in[3];
    const float* w_proj = (const float*)d_in[4];
    const float* b_proj = (const float*)d_in[5];
    float* out = (float*)d_out;

    __nv_bfloat16 *xn, *qkv, *att, *wqh, *wph;
    cudaGetSymbolAddress((void**)&xn,  g_xn);
    cudaGetSymbolAddress((void**)&qkv, g_qkv);
    cudaGetSymbolAddress((void**)&att, g_att);
    cudaGetSymbolAddress((void**)&wqh, g_wqkv_h);
    cudaGetSymbolAddress((void**)&wph, g_wproj_h);

    // 0) convert weights to bf16
    cvt_w_kernel<<<192, 256>>>(w_qkv, w_proj, wqh, wph);

    // 1) GroupNorm -> bf16
    gn_kernel<<<BATCH * GROUPS, 256>>>(x, gamma, beta, xn);

    // 2) QKV = W_qkv @ xn  -> bf16  (mma)
    cudaFuncSetAttribute(mma_gemm_kernel,
                         cudaFuncAttributeMaxDynamicSharedMemorySize, GEMM_SMEM);
    mma_gemm_kernel<<<dim3(NTOK / 64, (3 * CH) / 64, BATCH), 256, GEMM_SMEM>>>(
        wqh, xn, nullptr, nullptr, qkv, 3 * CH, 1);

    // 3) fused flash attention (Bq=128, bf16 mma, pipelined) -> bf16 att
    cudaFuncSetAttribute(attn_kernel,
                         cudaFuncAttributeMaxDynamicSharedMemorySize, ATTN_SMEM);
    attn_kernel<<<dim3(NTOK / 128, BATCH), 256, ATTN_SMEM>>>(qkv, att);

    // 4) out = x + W_proj @ att + b_proj  (mma, fp32 out)
    mma_gemm_kernel<<<dim3(NTOK / 64, CH / 64, BATCH), 256, GEMM_SMEM>>>(
        wph, att, b_proj, x, out, CH, 0);
}